// round 5
// baseline (speedup 1.0000x reference)
#include <cuda_runtime.h>
#include <cuda_fp16.h>
#include <cstdint>

#define B_  16
#define T_  512
#define K_  8
#define NI_ 256
#define UN_ 256
#define G_  1024   // 4*UNITS

// Hoisted x@W + b, stored GATE-INTERLEAVED: col j' = 4*u + g  (u=unit, g=gate).
__device__ float g_xw[(size_t)B_ * T_ * K_ * G_];

__device__ __forceinline__ uint32_t smem_u32(const void* p) {
    uint32_t a;
    asm("{ .reg .u64 t; cvta.to.shared.u64 t, %1; cvt.u32.u64 %0, t; }" : "=r"(a) : "l"(p));
    return a;
}
__device__ __forceinline__ float hsig(float v) {
    return fminf(fmaxf(fmaf(v, 0.2f, 0.5f), 0.0f), 1.0f);
}

#define LDSM4(r0, r1, r2, r3, addr)                                              \
    asm volatile("ldmatrix.sync.aligned.m8n8.x4.shared.b16 {%0,%1,%2,%3}, [%4];" \
                 : "=r"(r0), "=r"(r1), "=r"(r2), "=r"(r3) : "r"(addr))
#define LDSM4T(r0, r1, r2, r3, addr)                                             \
    asm volatile("ldmatrix.sync.aligned.m8n8.x4.trans.shared.b16 {%0,%1,%2,%3}, [%4];" \
                 : "=r"(r0), "=r"(r1), "=r"(r2), "=r"(r3) : "r"(addr))
#define MMA16816(d, a0, a1, a2, a3, b0, b1)                                      \
    asm volatile("mma.sync.aligned.m16n8k16.row.col.f32.f16.f16.f32 "            \
                 "{%0,%1,%2,%3}, {%4,%5,%6,%7}, {%8,%9}, {%0,%1,%2,%3};"         \
                 : "+f"(d[0]), "+f"(d[1]), "+f"(d[2]), "+f"(d[3])                \
                 : "r"(a0), "r"(a1), "r"(a2), "r"(a3), "r"(b0), "r"(b1))

// ---------------------------------------------------------------------------
// Kernel 1 (HMMA): g_xw[m][k][4u+g] = x[m,k,:] @ W[k][:, g*256+u] + b[k][g*256+u]
// Block: 128 m-rows x 128 interleaved cols (= 32 units x 4 gates), K=256 in smem.
// 8 warps, warp tile 64x32, m16n8k16 fp16->fp32.
// ---------------------------------------------------------------------------
#define AP 264   // As pitch in halves (528B rows: conflict-free ldmatrix)
#define BP 136   // Bs pitch in halves (272B rows)
#define SM1_A 0
#define SM1_B (128 * AP * 2)
#define SM1_TOT (SM1_B + 256 * BP * 2)

__global__ __launch_bounds__(256, 1) void gemm_xw_hmma(
    const float* __restrict__ x, const float* __restrict__ W,
    const float* __restrict__ bias)
{
    extern __shared__ char smem[];
    const uint32_t sb = smem_u32(smem);
    const int tid = threadIdx.x, w = tid >> 5, l = tid & 31;
    const int nb = blockIdx.x;          // 32-unit block (128 interleaved cols)
    const int bm = blockIdx.y * 128;
    const int k  = blockIdx.z;

    // Load A: x rows -> f16, row-major pitch AP.
    half* As = (half*)(smem + SM1_A);
    for (int idx = tid; idx < 128 * 64; idx += 256) {
        int r = idx >> 6, c4 = idx & 63;
        float4 v = *(const float4*)(x + ((size_t)(bm + r) * K_ + k) * NI_ + c4 * 4);
        __half2 h01 = __floats2half2_rn(v.x, v.y);
        __half2 h23 = __floats2half2_rn(v.z, v.w);
        uint2 pk = make_uint2(*(uint32_t*)&h01, *(uint32_t*)&h23);
        *(uint2*)(As + r * AP + c4 * 4) = pk;
    }
    // Load B: Bs[i][n'] = W[k][i][g*256 + nb*32 + u],  n' = 4u+g.
    half* Bs = (half*)(smem + SM1_B);
    for (int idx = tid; idx < 256 * 128; idx += 256) {
        int i = idx >> 7, np = idx & 127;
        int u = np >> 2, g = np & 3;
        Bs[i * BP + np] = __float2half_rn(
            W[((size_t)k * NI_ + i) * G_ + g * 256 + nb * 32 + u]);
    }
    __syncthreads();

    const int wm = w >> 2, wn = w & 3;  // warp: 64 m-rows, 32 n-cols
    float acc[4][4][4];
#pragma unroll
    for (int a = 0; a < 4; a++)
#pragma unroll
        for (int b = 0; b < 4; b++)
#pragma unroll
            for (int e = 0; e < 4; e++) acc[a][b][e] = 0.0f;

#pragma unroll
    for (int ks = 0; ks < 16; ks++) {
        uint32_t af[4][4], bf[2][4];
#pragma unroll
        for (int ma = 0; ma < 4; ma++) {
            uint32_t aaddr = sb + SM1_A
                + (uint32_t)(wm * 64 + ma * 16 + (l & 15)) * (AP * 2)
                + (uint32_t)ks * 32 + (uint32_t)(l >> 4) * 16;
            LDSM4(af[ma][0], af[ma][1], af[ma][2], af[ma][3], aaddr);
        }
#pragma unroll
        for (int n2 = 0; n2 < 2; n2++) {
            uint32_t baddr = sb + SM1_B
                + (uint32_t)(ks * 16 + ((l >> 3) & 1) * 8 + (l & 7)) * (BP * 2)
                + (uint32_t)(wn * 32 + n2 * 16 + (l >> 4) * 8) * 2;
            LDSM4T(bf[n2][0], bf[n2][1], bf[n2][2], bf[n2][3], baddr);
        }
#pragma unroll
        for (int ma = 0; ma < 4; ma++) {
            MMA16816(acc[ma][0], af[ma][0], af[ma][1], af[ma][2], af[ma][3], bf[0][0], bf[0][1]);
            MMA16816(acc[ma][1], af[ma][0], af[ma][1], af[ma][2], af[ma][3], bf[0][2], bf[0][3]);
            MMA16816(acc[ma][2], af[ma][0], af[ma][1], af[ma][2], af[ma][3], bf[1][0], bf[1][1]);
            MMA16816(acc[ma][3], af[ma][0], af[ma][1], af[ma][2], af[ma][3], bf[1][2], bf[1][3]);
        }
    }

    // Epilogue: + bias, store coalesced float2 (interleaved layout is contiguous).
#pragma unroll
    for (int nt = 0; nt < 4; nt++) {
        const int np = wn * 32 + nt * 8 + (l & 3) * 2;
        const int u = np >> 2, g = np & 3;
        const float b0 = __ldg(bias + (size_t)k * G_ + g * 256 + nb * 32 + u);
        const float b1 = __ldg(bias + (size_t)k * G_ + (g + 1) * 256 + nb * 32 + u);
#pragma unroll
        for (int ma = 0; ma < 4; ma++) {
            const int m0 = bm + wm * 64 + ma * 16 + (l >> 2);
            float* p0 = g_xw + ((size_t)m0 * K_ + k) * G_ + nb * 128 + np;
            float* p1 = g_xw + ((size_t)(m0 + 8) * K_ + k) * G_ + nb * 128 + np;
            *(float2*)p0 = make_float2(acc[ma][nt][0] + b0, acc[ma][nt][1] + b1);
            *(float2*)p1 = make_float2(acc[ma][nt][2] + b0, acc[ma][nt][3] + b1);
        }
    }
}

// ---------------------------------------------------------------------------
// Kernel 2: recurrence v2. Cluster of 4 CTAs per k; CTA r owns units
// [64r,64r+64) x 4 gates, gate-interleaved rows j = 4*uloc+g in UT smem.
// 16 warps; warp w owns 16 interleaved cols = units 4w..4w+3. State c in
// registers; update via 3 shuffles; one cluster barrier per step.
// ---------------------------------------------------------------------------
#define UTP 264                          // UT pitch (halves)
#define HP  264                          // H pitch (halves)
#define OFF_UT 0                         // 256 * 528 B
#define OFF_H  (256 * UTP * 2)           // 2 x 16 x 528 B
#define SM2_TOT (OFF_H + 2 * 16 * HP * 2)

__global__ __launch_bounds__(512, 1) __cluster_dims__(4, 1, 1)
void lstm_rec_mma2(const float* __restrict__ U, float* __restrict__ out)
{
    extern __shared__ char smem[];
    const uint32_t sb = smem_u32(smem);
    const int tid = threadIdx.x, w = tid >> 5, l = tid & 31;
    const int k = blockIdx.x >> 2;
    uint32_t rank;
    asm("mov.u32 %0, %%cluster_ctarank;" : "=r"(rank));

    // Load UT: row j = 4*jloc + g  <-  U[k][i][g*256 + rank*64 + jloc]
    {
        const int jloc = tid & 63, g = (tid >> 6) & 3, hsel = tid >> 8;
        const float* up = U + (size_t)k * NI_ * G_ + g * 256 + (int)rank * 64 + jloc;
        half* uts = (half*)(smem + OFF_UT) + (size_t)(4 * jloc + g) * UTP;
        for (int i = hsel * 128; i < hsel * 128 + 128; i++)
            uts[i] = __float2half_rn(up[(size_t)i * G_]);
    }
    for (int idx = tid; idx < 2 * 16 * HP; idx += 512)
        ((half*)(smem + OFF_H))[idx] = __ushort_as_half((unsigned short)0);
    __syncthreads();
    asm volatile("barrier.cluster.arrive.aligned;" ::: "memory");
    asm volatile("barrier.cluster.wait.aligned;" ::: "memory");

    const int  cell = (l >> 2) + (l & 1) * 8;   // my cell after pair split
    const bool eo   = (l & 1) == 0;             // even: gates {0,1}=(a,i)
    const uint32_t a_base = sb + OFF_H + (uint32_t)(l & 15) * (HP * 2)
                          + (uint32_t)(l >> 4) * 16;
    const uint32_t b_base = sb + OFF_UT
        + (uint32_t)(16 * w + ((l >> 4) & 1) * 8 + (l & 7)) * (UTP * 2)
        + (uint32_t)((l >> 3) & 1) * 16;

    float c0 = 0.0f, c1 = 0.0f;

    for (int t = 0; t < T_; t++) {
        // xw prefetch (interleaved layout): cols 4*(u) + 2*(l&1) + {0,1}
        float2 xlo[2], xhi[2];
#pragma unroll
        for (int nt = 0; nt < 2; nt++) {
            const int jp = 4 * ((int)rank * 64 + 4 * w + 2 * nt + ((l >> 1) & 1))
                         + (l & 1) * 2;
            const size_t base = (((size_t)(l >> 2) * T_ + t) * K_ + k) * G_ + jp;
            xlo[nt] = __ldg((const float2*)(g_xw + base));
            xhi[nt] = __ldg((const float2*)(g_xw + base + (size_t)8 * T_ * K_ * G_));
        }

        // MMA: Z[16 cells, 16 cols] over K=256
        float acc0[4] = {0, 0, 0, 0}, acc1[4] = {0, 0, 0, 0};
        uint32_t aaddr = a_base + (uint32_t)(t & 1) * (16 * HP * 2);
        uint32_t baddr = b_base;
#pragma unroll
        for (int ks = 0; ks < 16; ks++) {
            uint32_t a0, a1, a2, a3, b0, b1, b2, b3;
            LDSM4(a0, a1, a2, a3, aaddr);
            LDSM4(b0, b1, b2, b3, baddr);
            MMA16816(acc0, a0, a1, a2, a3, b0, b1);
            MMA16816(acc1, a0, a1, a2, a3, b2, b3);
            aaddr += 32; baddr += 32;
        }

        // Epilogue: z -> activations -> pair shuffles -> c/h in registers.
        float2 outv[2];
        int    outu[2];
#pragma unroll
        for (int nt = 0; nt < 2; nt++) {
            const float* acc = nt ? acc1 : acc0;
            float z0 = acc[0] + xlo[nt].x;
            float z1 = acc[1] + xlo[nt].y;
            float z2 = acc[2] + xhi[nt].x;
            float z3 = acc[3] + xhi[nt].y;
            float v0, v1, v2, v3;
            if (eo) { v0 = tanhf(z0); v1 = hsig(z1); v2 = tanhf(z2); v3 = hsig(z3); }
            else    { v0 = hsig(z0);  v1 = hsig(z1); v2 = hsig(z2);  v3 = hsig(z3); }
            // exchange: even sends (a_hi,i_hi)=(v2,v3); odd sends (f_lo,o_lo)=(v0,v1)
            float s0 = eo ? v2 : v0, s1 = eo ? v3 : v1;
            float r0 = __shfl_xor_sync(0xFFFFFFFFu, s0, 1);
            float r1 = __shfl_xor_sync(0xFFFFFFFFu, s1, 1);
            float A_ = eo ? v0 : r0;
            float I_ = eo ? v1 : r1;
            float F_ = eo ? r0 : v2;
            float O_ = eo ? r1 : v3;
            float& c = nt ? c1 : c0;
            c = fmaf(F_, c, A_ * I_);
            float h = O_ * tanhf(c);
            // pack adjacent unit (lanes l, l^2 share cell & parity)
            float hn = __shfl_xor_sync(0xFFFFFFFFu, h, 2);
            const int u = 4 * w + 2 * nt;          // even unit of the pair
            outv[nt] = make_float2(h, hn);
            outu[nt] = u;
            if ((l & 2) == 0) {
                __half2 hh = __floats2half2_rn(h, hn);
                uint32_t hb = *(uint32_t*)&hh;
                uint32_t laddr = sb + OFF_H + (uint32_t)((t + 1) & 1) * (16 * HP * 2)
                               + (uint32_t)cell * (HP * 2)
                               + (rank * 64u + (uint32_t)u) * 2u;
#pragma unroll
                for (int peer = 0; peer < 4; peer++) {
                    uint32_t ra;
                    asm("mapa.shared::cluster.u32 %0, %1, %2;" : "=r"(ra) : "r"(laddr), "r"(peer));
                    asm volatile("st.shared::cluster.b32 [%0], %1;" :: "r"(ra), "r"(hb) : "memory");
                }
            }
        }

        // Release DSMEM h stores; overlap global out stores with peers.
        asm volatile("barrier.cluster.arrive.aligned;" ::: "memory");
        if ((l & 2) == 0) {
#pragma unroll
            for (int nt = 0; nt < 2; nt++)
                *(float2*)(out + (((size_t)cell * T_ + t) * K_ + k) * UN_
                           + (size_t)rank * 64 + outu[nt]) = outv[nt];
        }
        asm volatile("barrier.cluster.wait.aligned;" ::: "memory");
    }
}

// ---------------------------------------------------------------------------
extern "C" void kernel_launch(void* const* d_in, const int* in_sizes, int n_in,
                              void* d_out, int out_size)
{
    const float* x = (const float*)d_in[0];
    const float* W = (const float*)d_in[1];
    const float* U = (const float*)d_in[2];
    const float* b = (const float*)d_in[3];
    float* out = (float*)d_out;

    cudaFuncSetAttribute(gemm_xw_hmma, cudaFuncAttributeMaxDynamicSharedMemorySize, SM1_TOT);
    dim3 g1(8, 64, 8);
    gemm_xw_hmma<<<g1, 256, SM1_TOT>>>(x, W, b);

    cudaFuncSetAttribute(lstm_rec_mma2, cudaFuncAttributeMaxDynamicSharedMemorySize, SM2_TOT);
    lstm_rec_mma2<<<K_ * 4, 512, SM2_TOT>>>(U, out);
}

// round 7
// speedup vs baseline: 1.3616x; 1.3616x over previous
#include <cuda_runtime.h>
#include <cuda_fp16.h>
#include <cstdint>

#define B_  16
#define T_  512
#define K_  8
#define NI_ 256
#define UN_ 256
#define G_  1024   // 4*UNITS

// Hoisted x@W + b. Column layout: gates {0,1}: col = 2*u + g (cols [0,512));
// gates {2,3}: col = 512 + 2*u + (g-2).
__device__ float g_xw[(size_t)B_ * T_ * K_ * G_];

__device__ __forceinline__ uint32_t smem_u32(const void* p) {
    uint32_t a;
    asm("{ .reg .u64 t; cvta.to.shared.u64 t, %1; cvt.u32.u64 %0, t; }" : "=r"(a) : "l"(p));
    return a;
}
__device__ __forceinline__ float hsig(float v) {
    return fminf(fmaxf(fmaf(v, 0.2f, 0.5f), 0.0f), 1.0f);
}

#define LDSM4(r0, r1, r2, r3, addr)                                              \
    asm volatile("ldmatrix.sync.aligned.m8n8.x4.shared.b16 {%0,%1,%2,%3}, [%4];" \
                 : "=r"(r0), "=r"(r1), "=r"(r2), "=r"(r3) : "r"(addr))
#define LDSM4T(r0, r1, r2, r3, addr)                                             \
    asm volatile("ldmatrix.sync.aligned.m8n8.x4.trans.shared.b16 {%0,%1,%2,%3}, [%4];" \
                 : "=r"(r0), "=r"(r1), "=r"(r2), "=r"(r3) : "r"(addr))
#define MMA16816(d, a0, a1, a2, a3, b0, b1)                                      \
    asm volatile("mma.sync.aligned.m16n8k16.row.col.f32.f16.f16.f32 "            \
                 "{%0,%1,%2,%3}, {%4,%5,%6,%7}, {%8,%9}, {%0,%1,%2,%3};"         \
                 : "+f"(d[0]), "+f"(d[1]), "+f"(d[2]), "+f"(d[3])                \
                 : "r"(a0), "r"(a1), "r"(a2), "r"(a3), "r"(b0), "r"(b1))

#define MBAR_WAIT(addr, ph) do {                                                          \
    uint32_t _done;                                                                       \
    asm volatile("{ .reg .pred p; mbarrier.try_wait.parity.acquire.cta.shared::cta.b64 "  \
                 "p, [%1], %2; selp.b32 %0,1,0,p; }"                                      \
                 : "=r"(_done) : "r"(addr), "r"(ph) : "memory");                          \
    while (!_done) {                                                                      \
        asm volatile("{ .reg .pred p; mbarrier.try_wait.parity.acquire.cta.shared::cta.b64 " \
                     "p, [%1], %2, 0x989680; selp.b32 %0,1,0,p; }"                        \
                     : "=r"(_done) : "r"(addr), "r"(ph) : "memory");                      \
    }                                                                                     \
} while (0)

// ---------------------------------------------------------------------------
// Kernel 1 (HMMA): hoisted x@W + b into g_xw with the paired-gate layout.
// ---------------------------------------------------------------------------
#define AP 264
#define BP 136
#define SM1_A 0
#define SM1_B (128 * AP * 2)
#define SM1_TOT (SM1_B + 256 * BP * 2)

__global__ __launch_bounds__(256, 1) void gemm_xw_hmma(
    const float* __restrict__ x, const float* __restrict__ W,
    const float* __restrict__ bias)
{
    extern __shared__ char smem[];
    const uint32_t sb = smem_u32(smem);
    const int tid = threadIdx.x, w = tid >> 5, l = tid & 31;
    const int nb = blockIdx.x;          // 32-unit block
    const int bm = blockIdx.y * 128;
    const int k  = blockIdx.z;

    half* As = (half*)(smem + SM1_A);
    for (int idx = tid; idx < 128 * 64; idx += 256) {
        int r = idx >> 6, c4 = idx & 63;
        float4 v = *(const float4*)(x + ((size_t)(bm + r) * K_ + k) * NI_ + c4 * 4);
        __half2 h01 = __floats2half2_rn(v.x, v.y);
        __half2 h23 = __floats2half2_rn(v.z, v.w);
        uint2 pk = make_uint2(*(uint32_t*)&h01, *(uint32_t*)&h23);
        *(uint2*)(As + r * AP + c4 * 4) = pk;
    }
    half* Bs = (half*)(smem + SM1_B);
    for (int idx = tid; idx < 256 * 128; idx += 256) {
        int i = idx >> 7, np = idx & 127;
        int g, u32;
        if (np < 64) { g = np & 1;       u32 = np >> 1; }
        else         { g = 2 + (np & 1); u32 = (np - 64) >> 1; }
        Bs[i * BP + np] = __float2half_rn(
            W[((size_t)k * NI_ + i) * G_ + g * 256 + nb * 32 + u32]);
    }
    __syncthreads();

    const int wm = w >> 2, wn = w & 3;
    float acc[4][4][4];
#pragma unroll
    for (int a = 0; a < 4; a++)
#pragma unroll
        for (int b = 0; b < 4; b++)
#pragma unroll
            for (int e = 0; e < 4; e++) acc[a][b][e] = 0.0f;

#pragma unroll
    for (int ks = 0; ks < 16; ks++) {
        uint32_t af[4][4], bf[2][4];
#pragma unroll
        for (int ma = 0; ma < 4; ma++) {
            uint32_t aaddr = sb + SM1_A
                + (uint32_t)(wm * 64 + ma * 16 + (l & 15)) * (AP * 2)
                + (uint32_t)ks * 32 + (uint32_t)(l >> 4) * 16;
            LDSM4(af[ma][0], af[ma][1], af[ma][2], af[ma][3], aaddr);
        }
#pragma unroll
        for (int n2 = 0; n2 < 2; n2++) {
            uint32_t baddr = sb + SM1_B
                + (uint32_t)(ks * 16 + ((l >> 3) & 1) * 8 + (l & 7)) * (BP * 2)
                + (uint32_t)(wn * 32 + n2 * 16 + (l >> 4) * 8) * 2;
            LDSM4T(bf[n2][0], bf[n2][1], bf[n2][2], bf[n2][3], baddr);
        }
#pragma unroll
        for (int ma = 0; ma < 4; ma++) {
            MMA16816(acc[ma][0], af[ma][0], af[ma][1], af[ma][2], af[ma][3], bf[0][0], bf[0][1]);
            MMA16816(acc[ma][1], af[ma][0], af[ma][1], af[ma][2], af[ma][3], bf[0][2], bf[0][3]);
            MMA16816(acc[ma][2], af[ma][0], af[ma][1], af[ma][2], af[ma][3], bf[1][0], bf[1][1]);
            MMA16816(acc[ma][3], af[ma][0], af[ma][1], af[ma][2], af[ma][3], bf[1][2], bf[1][3]);
        }
    }

#pragma unroll
    for (int nt = 0; nt < 4; nt++) {
        const int np = wn * 32 + nt * 8 + (l & 3) * 2;
        int g0, u32, col;
        if (np < 64) { g0 = 0; u32 = np >> 1;        col = nb * 64 + np; }
        else         { g0 = 2; u32 = (np - 64) >> 1; col = 512 + nb * 64 + (np - 64); }
        const float b0 = __ldg(bias + (size_t)k * G_ + g0 * 256 + nb * 32 + u32);
        const float b1 = __ldg(bias + (size_t)k * G_ + (g0 + 1) * 256 + nb * 32 + u32);
#pragma unroll
        for (int ma = 0; ma < 4; ma++) {
            const int m0 = bm + wm * 64 + ma * 16 + (l >> 2);
            float* p0 = g_xw + ((size_t)m0 * K_ + k) * G_ + col;
            float* p1 = g_xw + ((size_t)(m0 + 8) * K_ + k) * G_ + col;
            *(float2*)p0 = make_float2(acc[ma][nt][0] + b0, acc[ma][nt][1] + b1);
            *(float2*)p1 = make_float2(acc[ma][nt][2] + b0, acc[ma][nt][3] + b1);
        }
    }
}

// ---------------------------------------------------------------------------
// Kernel 2: recurrence v3 (fixed). 4-CTA cluster per k; bulk-DSMEM h ring.
// FIX vs R6: init pre-arms ONLY barrier 1 (fills from step-0 copies).
// Barrier 0's first fill (end of step 1) is armed by the loop at t=0.
// Double-arming barrier 0 was UB (2 arrives on a count-1 barrier) + deadlock.
// ---------------------------------------------------------------------------
#define UTP   264                         // UT pitch in halves (528B rows)
#define SLAB  2304                        // 16 * 144
#define HBUF  (4 * SLAB)                  // 9216
#define OFF_UT  0                         // 135168 B
#define OFF_H   (256 * UTP * 2)           // 2 buffers x 9216
#define OFF_STG (OFF_H + 2 * HBUF)        // 2 x 2304
#define OFF_MB  (OFF_STG + 2 * SLAB)      // 2 mbarriers
#define SM2_TOT (OFF_MB + 32)

__global__ __launch_bounds__(256, 1) __cluster_dims__(4, 1, 1)
void lstm_rec_v3(const float* __restrict__ U, float* __restrict__ out)
{
    extern __shared__ char smem[];
    const uint32_t sb = smem_u32(smem);
    const int tid = threadIdx.x, w = tid >> 5, l = tid & 31;
    const int k = blockIdx.x >> 2;
    uint32_t rank;
    asm("mov.u32 %0, %%cluster_ctarank;" : "=r"(rank));

    // Load UT (one row per thread).
    {
        const int j = tid;
        int u, g;
        if (j < 128) { u = j >> 1;         g = j & 1; }
        else         { u = (j - 128) >> 1; g = 2 + (j & 1); }
        const float* up = U + (size_t)k * NI_ * G_ + g * 256 + (int)rank * 64 + u;
        half* uts = (half*)(smem + OFF_UT) + (size_t)j * UTP;
        for (int i = 0; i < 256; i++)
            uts[i] = __float2half_rn(up[(size_t)i * G_]);
    }
    // Zero H buffer 0 (h0 = 0).
    for (int idx = tid; idx < HBUF / 4; idx += 256)
        ((uint32_t*)(smem + OFF_H))[idx] = 0u;
    if (tid == 0) {
        asm volatile("mbarrier.init.shared.b64 [%0], %1;" :: "r"(sb + OFF_MB), "r"(1u) : "memory");
        asm volatile("mbarrier.init.shared.b64 [%0], %1;" :: "r"(sb + OFF_MB + 8), "r"(1u) : "memory");
        // Pre-arm ONLY barrier 1: it receives the copies issued at end of
        // step 0. Barrier 0 is armed inside the loop at t=0.
        asm volatile("mbarrier.arrive.expect_tx.shared.b64 _, [%0], %1;"
                     :: "r"(sb + OFF_MB + 8), "r"(4u * SLAB) : "memory");
    }
    __syncthreads();
    asm volatile("barrier.cluster.arrive.aligned;" ::: "memory");
    asm volatile("barrier.cluster.wait.aligned;" ::: "memory");

    // Per-lane constants.
    const int u0    = 8 * w + (l & 3);          // first unit (second = u0+4)
    const int cell0 = l >> 2;                   // cells: cell0, cell0+8
    const uint32_t aBase = sb + OFF_H + (uint32_t)(l & 15) * 144 + (uint32_t)(l >> 4) * 16;
    const uint32_t bLo = sb + OFF_UT
        + (uint32_t)(16 * w + ((l >> 4) & 1) * 8 + (l & 7)) * (UTP * 2)
        + (uint32_t)((l >> 3) & 1) * 16;
    const uint32_t bHi = bLo + 128u * (UTP * 2);
    const float* xwc0 = g_xw + ((size_t)cell0 * T_ * K_ + k) * G_;
    const size_t  C8  = (size_t)8 * T_ * K_ * G_;
    const int colLo = 2 * ((int)rank * 64 + u0);
    const bool evn = (l & 1) == 0;
    float c00 = 0.f, c01 = 0.f, c10 = 0.f, c11 = 0.f;  // c[unit][cell]
    int ph0 = 0, ph1 = 0;

    for (int t = 0; t < T_; t++) {
        const int p = t & 1;
        // xw prefetch (8 float2): [unit e][gates lo/hi][cell lo/hi]
        const float* xr = xwc0 + (size_t)t * (K_ * G_);
        float2 xw[8];
        xw[0] = __ldg((const float2*)(xr + colLo));
        xw[1] = __ldg((const float2*)(xr + colLo + 8));
        xw[2] = __ldg((const float2*)(xr + colLo + 512));
        xw[3] = __ldg((const float2*)(xr + colLo + 520));
        xw[4] = __ldg((const float2*)(xr + C8 + colLo));
        xw[5] = __ldg((const float2*)(xr + C8 + colLo + 8));
        xw[6] = __ldg((const float2*)(xr + C8 + colLo + 512));
        xw[7] = __ldg((const float2*)(xr + C8 + colLo + 520));

        if (t > 0) {
            if (p) { MBAR_WAIT(sb + OFF_MB + 8, (uint32_t)ph1); ph1 ^= 1; }
            else   { MBAR_WAIT(sb + OFF_MB,     (uint32_t)ph0); ph0 ^= 1; }
        }
        if (tid == 0)
            asm volatile("mbarrier.arrive.expect_tx.shared.b64 _, [%0], %1;"
                         :: "r"(sb + OFF_MB + (uint32_t)p * 8), "r"(4u * SLAB) : "memory");

        // MMA: Z[16 cells, 32 cols] over K=256.
        float aL0[4] = {0,0,0,0}, aL1[4] = {0,0,0,0};
        float aH0[4] = {0,0,0,0}, aH1[4] = {0,0,0,0};
        const uint32_t aA = aBase + (uint32_t)p * HBUF;
        uint32_t bl = bLo, bh = bHi;
#pragma unroll
        for (int ks = 0; ks < 16; ks++) {
            uint32_t a0, a1, a2, a3, p0, p1, p2, p3, q0, q1, q2, q3;
            LDSM4(a0, a1, a2, a3, aA + (uint32_t)(ks >> 2) * SLAB + (uint32_t)(ks & 3) * 32);
            LDSM4(p0, p1, p2, p3, bl);
            LDSM4(q0, q1, q2, q3, bh);
            MMA16816(aL0, a0, a1, a2, a3, p0, p1);
            MMA16816(aL1, a0, a1, a2, a3, p2, p3);
            MMA16816(aH0, a0, a1, a2, a3, q0, q1);
            MMA16816(aH1, a0, a1, a2, a3, q2, q3);
            bl += 32; bh += 32;
        }

        // Epilogue: all 4 gates in-lane.
        float h[2][2];
#pragma unroll
        for (int e = 0; e < 2; e++) {
            const float* accL = e ? aL1 : aL0;
            const float* accH = e ? aH1 : aH0;
#pragma unroll
            for (int cc = 0; cc < 2; cc++) {
                float2 xl = xw[e + cc * 4];
                float2 xh = xw[2 + e + cc * 4];
                float a = tanhf(accL[cc * 2 + 0] + xl.x);
                float i = hsig (accL[cc * 2 + 1] + xl.y);
                float f = hsig (accH[cc * 2 + 0] + xh.x);
                float o = hsig (accH[cc * 2 + 1] + xh.y);
                float& c = e ? (cc ? c11 : c10) : (cc ? c01 : c00);
                c = fmaf(f, c, a * i);
                h[e][cc] = o * tanhf(c);
            }
        }

        // Pack pairs (shfl with lane^1), stage to slab + global out.
        const uint32_t stg = sb + OFF_STG + (uint32_t)p * SLAB;
#pragma unroll
        for (int e = 0; e < 2; e++) {
            float r0 = __shfl_xor_sync(0xFFFFFFFFu, h[e][0], 1);
            float r8 = __shfl_xor_sync(0xFFFFFFFFu, h[e][1], 1);
            int up, cs;
            float lo, hi;
            if (evn) { up = u0 + 4 * e;     cs = cell0;     lo = h[e][0]; hi = r0; }
            else     { up = u0 - 1 + 4 * e; cs = cell0 + 8; lo = r8;      hi = h[e][1]; }
            __half2 hh = __floats2half2_rn(lo, hi);
            *(__half2*)(smem + (stg - sb) + cs * 144 + up * 2) = hh;
            *(float2*)(out + (((size_t)cs * T_ + t) * K_ + k) * UN_
                       + (size_t)rank * 64 + up) = make_float2(lo, hi);
        }

        __syncthreads();
        if (tid == 0) {
            asm volatile("fence.proxy.async;" ::: "memory");
            const uint32_t dstL = sb + OFF_H + (uint32_t)(p ^ 1) * HBUF + rank * SLAB;
            const uint32_t mbL  = sb + OFF_MB + (uint32_t)(p ^ 1) * 8;
#pragma unroll
            for (int peer = 0; peer < 4; peer++) {
                uint32_t dstR, mbR;
                asm("mapa.shared::cluster.u32 %0, %1, %2;" : "=r"(dstR) : "r"(dstL), "r"(peer));
                asm("mapa.shared::cluster.u32 %0, %1, %2;" : "=r"(mbR)  : "r"(mbL),  "r"(peer));
                asm volatile(
                    "cp.async.bulk.shared::cluster.shared::cta.mbarrier::complete_tx::bytes "
                    "[%0], [%1], %2, [%3];"
                    :: "r"(dstR), "r"(stg), "r"((uint32_t)SLAB), "r"(mbR) : "memory");
            }
        }
    }

    // Keep smem alive until all peers' last bulks land.
    asm volatile("barrier.cluster.arrive.aligned;" ::: "memory");
    asm volatile("barrier.cluster.wait.aligned;" ::: "memory");
}

// ---------------------------------------------------------------------------
extern "C" void kernel_launch(void* const* d_in, const int* in_sizes, int n_in,
                              void* d_out, int out_size)
{
    const float* x = (const float*)d_in[0];
    const float* W = (const float*)d_in[1];
    const float* U = (const float*)d_in[2];
    const float* b = (const float*)d_in[3];
    float* out = (float*)d_out;

    cudaFuncSetAttribute(gemm_xw_hmma, cudaFuncAttributeMaxDynamicSharedMemorySize, SM1_TOT);
    dim3 g1(8, 64, 8);
    gemm_xw_hmma<<<g1, 256, SM1_TOT>>>(x, W, b);

    cudaFuncSetAttribute(lstm_rec_v3, cudaFuncAttributeMaxDynamicSharedMemorySize, SM2_TOT);
    lstm_rec_v3<<<K_ * 4, 256, SM2_TOT>>>(U, out);
}

// round 8
// speedup vs baseline: 1.4441x; 1.0606x over previous
#include <cuda_runtime.h>
#include <cuda_fp16.h>
#include <cstdint>

#define B_  16
#define T_  512
#define K_  8
#define NI_ 256
#define UN_ 256
#define G_  1024   // 4*UNITS

// Hoisted x@W + b, GATE-INTERLEAVED: col = 4*u + g  (u=unit 0..255, g=gate).
__device__ float g_xw[(size_t)B_ * T_ * K_ * G_];

__device__ __forceinline__ uint32_t smem_u32(const void* p) {
    uint32_t a;
    asm("{ .reg .u64 t; cvta.to.shared.u64 t, %1; cvt.u32.u64 %0, t; }" : "=r"(a) : "l"(p));
    return a;
}
__device__ __forceinline__ float hsig(float v) {
    return fminf(fmaxf(fmaf(v, 0.2f, 0.5f), 0.0f), 1.0f);
}

#define LDSM4(r0, r1, r2, r3, addr)                                              \
    asm volatile("ldmatrix.sync.aligned.m8n8.x4.shared.b16 {%0,%1,%2,%3}, [%4];" \
                 : "=r"(r0), "=r"(r1), "=r"(r2), "=r"(r3) : "r"(addr))
#define LDSM4T(r0, r1, r2, r3, addr)                                             \
    asm volatile("ldmatrix.sync.aligned.m8n8.x4.trans.shared.b16 {%0,%1,%2,%3}, [%4];" \
                 : "=r"(r0), "=r"(r1), "=r"(r2), "=r"(r3) : "r"(addr))
#define MMA16816(d, a0, a1, a2, a3, b0, b1)                                      \
    asm volatile("mma.sync.aligned.m16n8k16.row.col.f32.f16.f16.f32 "            \
                 "{%0,%1,%2,%3}, {%4,%5,%6,%7}, {%8,%9}, {%0,%1,%2,%3};"         \
                 : "+f"(d[0]), "+f"(d[1]), "+f"(d[2]), "+f"(d[3])                \
                 : "r"(a0), "r"(a1), "r"(a2), "r"(a3), "r"(b0), "r"(b1))

#define MBAR_WAIT(addr, ph) do {                                                          \
    uint32_t _done;                                                                       \
    asm volatile("{ .reg .pred p; mbarrier.try_wait.parity.acquire.cta.shared::cta.b64 "  \
                 "p, [%1], %2; selp.b32 %0,1,0,p; }"                                      \
                 : "=r"(_done) : "r"(addr), "r"(ph) : "memory");                          \
    while (!_done) {                                                                      \
        asm volatile("{ .reg .pred p; mbarrier.try_wait.parity.acquire.cta.shared::cta.b64 " \
                     "p, [%1], %2, 0x989680; selp.b32 %0,1,0,p; }"                        \
                     : "=r"(_done) : "r"(addr), "r"(ph) : "memory");                      \
    }                                                                                     \
} while (0)

// ---------------------------------------------------------------------------
// Kernel 1 (HMMA): x@W + b into g_xw, col = 4u+g (R5-proven layout/epilogue).
// ---------------------------------------------------------------------------
#define AP 264
#define BP 136
#define SM1_A 0
#define SM1_B (128 * AP * 2)
#define SM1_TOT (SM1_B + 256 * BP * 2)

__global__ __launch_bounds__(256, 1) void gemm_xw_hmma(
    const float* __restrict__ x, const float* __restrict__ W,
    const float* __restrict__ bias)
{
    extern __shared__ char smem[];
    const uint32_t sb = smem_u32(smem);
    const int tid = threadIdx.x, w = tid >> 5, l = tid & 31;
    const int nb = blockIdx.x;          // 32-unit block (128 interleaved cols)
    const int bm = blockIdx.y * 128;
    const int k  = blockIdx.z;

    half* As = (half*)(smem + SM1_A);
    for (int idx = tid; idx < 128 * 64; idx += 256) {
        int r = idx >> 6, c4 = idx & 63;
        float4 v = *(const float4*)(x + ((size_t)(bm + r) * K_ + k) * NI_ + c4 * 4);
        __half2 h01 = __floats2half2_rn(v.x, v.y);
        __half2 h23 = __floats2half2_rn(v.z, v.w);
        uint2 pk = make_uint2(*(uint32_t*)&h01, *(uint32_t*)&h23);
        *(uint2*)(As + r * AP + c4 * 4) = pk;
    }
    // Bs[i][np] = W[k][i][g*256 + nb*32 + u],  np = 4*u_local + g
    half* Bs = (half*)(smem + SM1_B);
    for (int idx = tid; idx < 256 * 128; idx += 256) {
        int i = idx >> 7, np = idx & 127;
        int u = np >> 2, g = np & 3;
        Bs[i * BP + np] = __float2half_rn(
            W[((size_t)k * NI_ + i) * G_ + g * 256 + nb * 32 + u]);
    }
    __syncthreads();

    const int wm = w >> 2, wn = w & 3;
    float acc[4][4][4];
#pragma unroll
    for (int a = 0; a < 4; a++)
#pragma unroll
        for (int b = 0; b < 4; b++)
#pragma unroll
            for (int e = 0; e < 4; e++) acc[a][b][e] = 0.0f;

#pragma unroll
    for (int ks = 0; ks < 16; ks++) {
        uint32_t af[4][4], bf[2][4];
#pragma unroll
        for (int ma = 0; ma < 4; ma++) {
            uint32_t aaddr = sb + SM1_A
                + (uint32_t)(wm * 64 + ma * 16 + (l & 15)) * (AP * 2)
                + (uint32_t)ks * 32 + (uint32_t)(l >> 4) * 16;
            LDSM4(af[ma][0], af[ma][1], af[ma][2], af[ma][3], aaddr);
        }
#pragma unroll
        for (int n2 = 0; n2 < 2; n2++) {
            uint32_t baddr = sb + SM1_B
                + (uint32_t)(ks * 16 + ((l >> 3) & 1) * 8 + (l & 7)) * (BP * 2)
                + (uint32_t)(wn * 32 + n2 * 16 + (l >> 4) * 8) * 2;
            LDSM4T(bf[n2][0], bf[n2][1], bf[n2][2], bf[n2][3], baddr);
        }
#pragma unroll
        for (int ma = 0; ma < 4; ma++) {
            MMA16816(acc[ma][0], af[ma][0], af[ma][1], af[ma][2], af[ma][3], bf[0][0], bf[0][1]);
            MMA16816(acc[ma][1], af[ma][0], af[ma][1], af[ma][2], af[ma][3], bf[0][2], bf[0][3]);
            MMA16816(acc[ma][2], af[ma][0], af[ma][1], af[ma][2], af[ma][3], bf[1][0], bf[1][1]);
            MMA16816(acc[ma][3], af[ma][0], af[ma][1], af[ma][2], af[ma][3], bf[1][2], bf[1][3]);
        }
    }

#pragma unroll
    for (int nt = 0; nt < 4; nt++) {
        const int np = wn * 32 + nt * 8 + (l & 3) * 2;
        const int u = np >> 2, g = np & 3;
        const float b0 = __ldg(bias + (size_t)k * G_ + g * 256 + nb * 32 + u);
        const float b1 = __ldg(bias + (size_t)k * G_ + (g + 1) * 256 + nb * 32 + u);
#pragma unroll
        for (int ma = 0; ma < 4; ma++) {
            const int m0 = bm + wm * 64 + ma * 16 + (l >> 2);
            float* p0 = g_xw + ((size_t)m0 * K_ + k) * G_ + nb * 128 + np;
            float* p1 = g_xw + ((size_t)(m0 + 8) * K_ + k) * G_ + nb * 128 + np;
            *(float2*)p0 = make_float2(acc[ma][nt][0] + b0, acc[ma][nt][1] + b1);
            *(float2*)p1 = make_float2(acc[ma][nt][2] + b0, acc[ma][nt][3] + b1);
        }
    }
}

// ---------------------------------------------------------------------------
// Kernel 2: recurrence v4 — transposed MMA, U in REGISTERS.
// Z^T[zcol, cell] = U^T @ H^T : M = 256 zcols (16 warps x 16), N = 16 cells,
// K = 256 units. U A-frags ldmatrix'd ONCE into 64 regs/lane. Per-step smem
// traffic = streamed H only. Exchange protocol identical to R7.
// UT scratch row (16w + rr): unit_local = 4w + (rr&3), gate = rr>>2.
// ---------------------------------------------------------------------------
#define UTP   264                         // UT scratch pitch (halves)
#define SLAB  2304                        // 16 cells * 144 B
#define HBUF  (4 * SLAB)                  // 9216
#define OFF_H   0                         // 2 buffers x 9216
#define OFF_STG (2 * HBUF)                // 2 x 2304
#define OFF_MB  (OFF_STG + 2 * SLAB)      // 2 mbarriers
#define OFF_UT  24576                     // scratch, 256 rows x 528 B
#define SM2_TOT (OFF_UT + 256 * UTP * 2)  // 159744

__global__ __launch_bounds__(512, 1) __cluster_dims__(4, 1, 1)
void lstm_rec_v4(const float* __restrict__ U, float* __restrict__ out)
{
    extern __shared__ char smem[];
    const uint32_t sb = smem_u32(smem);
    const int tid = threadIdx.x, w = tid >> 5, l = tid & 31;
    const int k = blockIdx.x >> 2;
    uint32_t rank;
    asm("mov.u32 %0, %%cluster_ctarank;" : "=r"(rank));

    // --- Load UT scratch (2 threads per row) ---
    {
        const int j = tid >> 1, hf = tid & 1;
        const int wq = j >> 4, rr = j & 15;
        const int uloc = 4 * wq + (rr & 3), g = rr >> 2;
        const float* up = U + (size_t)k * NI_ * G_ + g * 256 + (int)rank * 64 + uloc;
        half* uts = (half*)(smem + OFF_UT) + (size_t)j * UTP;
        for (int i = hf * 128; i < hf * 128 + 128; i++)
            uts[i] = __float2half_rn(up[(size_t)i * G_]);
    }
    // Zero H buffer 0.
    for (int idx = tid; idx < HBUF / 4; idx += 512)
        ((uint32_t*)(smem + OFF_H))[idx] = 0u;
    if (tid == 0) {
        asm volatile("mbarrier.init.shared.b64 [%0], %1;" :: "r"(sb + OFF_MB), "r"(1u) : "memory");
        asm volatile("mbarrier.init.shared.b64 [%0], %1;" :: "r"(sb + OFF_MB + 8), "r"(1u) : "memory");
        // Pre-arm ONLY buffer-1 barrier (receives end-of-step-0 copies).
        asm volatile("mbarrier.arrive.expect_tx.shared.b64 _, [%0], %1;"
                     :: "r"(sb + OFF_MB + 8), "r"(4u * SLAB) : "memory");
    }
    __syncthreads();

    // --- UT -> A-frag registers (once) ---
    uint32_t Af[16][4];
    {
        const uint32_t abase = sb + OFF_UT
            + (uint32_t)(16 * w + (l & 15)) * (UTP * 2) + (uint32_t)(l >> 4) * 16;
#pragma unroll
        for (int ks = 0; ks < 16; ks++)
            LDSM4(Af[ks][0], Af[ks][1], Af[ks][2], Af[ks][3], abase + ks * 32);
    }

    asm volatile("barrier.cluster.arrive.aligned;" ::: "memory");
    asm volatile("barrier.cluster.wait.aligned;" ::: "memory");

    // --- Per-lane constants ---
    const bool lo16 = (l < 16);
    const int  uloc = 4 * w + ((l >> 2) & 3);            // unit (local 0..63)
    const int  cell0 = 2 * (l & 3) + (lo16 ? 0 : 1);     // cells cell0, cell0+8
    const int  colx = 4 * ((int)rank * 64 + uloc);       // xw col base (4u+g)
    const uint32_t hBase = sb + OFF_H + (uint32_t)(l & 15) * 144 + (uint32_t)(l >> 4) * 16;
    const float* xw0p = g_xw + ((size_t)cell0 * T_ * K_ + k) * G_ + colx;
    const float* xw1p = g_xw + ((size_t)(cell0 + 8) * T_ * K_ + k) * G_ + colx;
    float c0 = 0.0f, c1 = 0.0f;
    int ph0 = 0, ph1 = 0;

    for (int t = 0; t < T_; t++) {
        const int p = t & 1;

        // xw prefetch: all 4 gates of (unit, cell) as float4.
        float4 xwa = __ldg((const float4*)(xw0p + (size_t)t * (K_ * G_)));
        float4 xwb = __ldg((const float4*)(xw1p + (size_t)t * (K_ * G_)));

        if (t > 0) {
            if (p) { MBAR_WAIT(sb + OFF_MB + 8, (uint32_t)ph1); ph1 ^= 1; }
            else   { MBAR_WAIT(sb + OFF_MB,     (uint32_t)ph0); ph0 ^= 1; }
        }
        if (tid == 0)
            asm volatile("mbarrier.arrive.expect_tx.shared.b64 _, [%0], %1;"
                         :: "r"(sb + OFF_MB + (uint32_t)p * 8), "r"(4u * SLAB) : "memory");

        // MMA: Z^T[16 zcols, 16 cells] over K=256. Streamed operand = H.
        float dLo[4] = {0, 0, 0, 0}, dHi[4] = {0, 0, 0, 0};
        const uint32_t hA = hBase + (uint32_t)p * HBUF;
#pragma unroll
        for (int ks = 0; ks < 16; ks++) {
            uint32_t t0, t1, t2, t3;
            LDSM4(t0, t1, t2, t3, hA + (uint32_t)(ks >> 2) * SLAB + (uint32_t)(ks & 3) * 32);
            MMA16816(dLo, Af[ks][0], Af[ks][1], Af[ks][2], Af[ks][3], t0, t2);
            MMA16816(dHi, Af[ks][0], Af[ks][1], Af[ks][2], Af[ks][3], t1, t3);
        }

        // Redistribute gates across lane-pair (l, l^16): 4 independent shuffles.
        float xa = __shfl_xor_sync(0xFFFFFFFFu, lo16 ? dLo[1] : dLo[0], 16);
        float xb = __shfl_xor_sync(0xFFFFFFFFu, lo16 ? dLo[3] : dLo[2], 16);
        float xc = __shfl_xor_sync(0xFFFFFFFFu, lo16 ? dHi[1] : dHi[0], 16);
        float xd = __shfl_xor_sync(0xFFFFFFFFu, lo16 ? dHi[3] : dHi[2], 16);

        float zA0, zA1, zA2, zA3, zB0, zB1, zB2, zB3;
        if (lo16) { zA0 = dLo[0]; zA1 = xa;     zA2 = dLo[2]; zA3 = xb;
                    zB0 = dHi[0]; zB1 = xc;     zB2 = dHi[2]; zB3 = xd; }
        else      { zA0 = xa;     zA1 = dLo[1]; zA2 = xb;     zA3 = dLo[3];
                    zB0 = xc;     zB1 = dHi[1]; zB2 = xd;     zB3 = dHi[3]; }

        // Epilogue: 2 full (unit, cell) updates in registers.
        float av0 = tanhf(zA0 + xwa.x);
        float iv0 = hsig (zA1 + xwa.y);
        float fv0 = hsig (zA2 + xwa.z);
        float ov0 = hsig (zA3 + xwa.w);
        c0 = fmaf(fv0, c0, av0 * iv0);
        float h0 = ov0 * tanhf(c0);

        float av1 = tanhf(zB0 + xwb.x);
        float iv1 = hsig (zB1 + xwb.y);
        float fv1 = hsig (zB2 + xwb.z);
        float ov1 = hsig (zB3 + xwb.w);
        c1 = fmaf(fv1, c1, av1 * iv1);
        float h1 = ov1 * tanhf(c1);

        // Stage (f16) + global out (fp32).
        const uint32_t stgOff = OFF_STG + (uint32_t)p * SLAB;
        *(half*)(smem + stgOff + cell0 * 144 + uloc * 2)       = __float2half_rn(h0);
        *(half*)(smem + stgOff + (cell0 + 8) * 144 + uloc * 2) = __float2half_rn(h1);
        out[(((size_t)cell0 * T_ + t) * K_ + k) * UN_ + (size_t)rank * 64 + uloc] = h0;
        out[(((size_t)(cell0 + 8) * T_ + t) * K_ + k) * UN_ + (size_t)rank * 64 + uloc] = h1;

        __syncthreads();
        if (tid == 0) {
            asm volatile("fence.proxy.async;" ::: "memory");
            const uint32_t src  = sb + stgOff;
            const uint32_t dstL = sb + OFF_H + (uint32_t)(p ^ 1) * HBUF + rank * SLAB;
            const uint32_t mbL  = sb + OFF_MB + (uint32_t)(p ^ 1) * 8;
#pragma unroll
            for (int peer = 0; peer < 4; peer++) {
                uint32_t dstR, mbR;
                asm("mapa.shared::cluster.u32 %0, %1, %2;" : "=r"(dstR) : "r"(dstL), "r"(peer));
                asm("mapa.shared::cluster.u32 %0, %1, %2;" : "=r"(mbR)  : "r"(mbL),  "r"(peer));
                asm volatile(
                    "cp.async.bulk.shared::cluster.shared::cta.mbarrier::complete_tx::bytes "
                    "[%0], [%1], %2, [%3];"
                    :: "r"(dstR), "r"(src), "r"((uint32_t)SLAB), "r"(mbR) : "memory");
            }
        }
    }

    // Keep smem alive until all peers' last bulks land.
    asm volatile("barrier.cluster.arrive.aligned;" ::: "memory");
    asm volatile("barrier.cluster.wait.aligned;" ::: "memory");
}

// ---------------------------------------------------------------------------
extern "C" void kernel_launch(void* const* d_in, const int* in_sizes, int n_in,
                              void* d_out, int out_size)
{
    const float* x = (const float*)d_in[0];
    const float* W = (const float*)d_in[1];
    const float* U = (const float*)d_in[2];
    const float* b = (const float*)d_in[3];
    float* out = (float*)d_out;

    cudaFuncSetAttribute(gemm_xw_hmma, cudaFuncAttributeMaxDynamicSharedMemorySize, SM1_TOT);
    dim3 g1(8, 64, 8);
    gemm_xw_hmma<<<g1, 256, SM1_TOT>>>(x, W, b);

    cudaFuncSetAttribute(lstm_rec_v4, cudaFuncAttributeMaxDynamicSharedMemorySize, SM2_TOT);
    lstm_rec_v4<<<K_ * 4, 512, SM2_TOT>>>(U, out);
}